// round 3
// baseline (speedup 1.0000x reference)
#include <cuda_runtime.h>
#include <cstdint>

#define NLEV   14
#define TMASK  524287u        // (1<<19)-1
#define PRIME1 2654435761u
#define PRIME2 805459861u
#define MAXN   500000
#define DIN    36
#define W      64

// Scratch for encoded features [N, 28] (bss, not an allocation)
__device__ float g_feats[(size_t)MAXN * 28];

// floor(16 * 1.32^l), l = 0..13 (double math, matches numpy)
__device__ __constant__ float c_res[NLEV] =
    {16.f, 21.f, 27.f, 36.f, 48.f, 64.f, 84.f, 111.f,
     147.f, 194.f, 256.f, 339.f, 447.f, 590.f};

// ---------------------------------------------------------------------------
// Kernel 1: hash-grid encode. One thread per point. 14 levels x 8 corners
// of float2 gathers from L2-resident tables, smoothstep trilinear blend.
// ---------------------------------------------------------------------------
__global__ void __launch_bounds__(256)
encode_kernel(const float* __restrict__ x,
              const float* __restrict__ tables,
              const float* __restrict__ bbox,
              int n)
{
    int p = blockIdx.x * blockDim.x + threadIdx.x;
    if (p >= n) return;

    float lo0 = __ldg(bbox + 0), lo1 = __ldg(bbox + 1), lo2 = __ldg(bbox + 2);
    float hi0 = __ldg(bbox + 3), hi1 = __ldg(bbox + 4), hi2 = __ldg(bbox + 5);

    float xv0 = __ldg(x + (size_t)p * 3 + 0);
    float xv1 = __ldg(x + (size_t)p * 3 + 1);
    float xv2 = __ldg(x + (size_t)p * 3 + 2);

    float xn0 = (xv0 - lo0) / (hi0 - lo0);
    float xn1 = (xv1 - lo1) / (hi1 - lo1);
    float xn2 = (xv2 - lo2) / (hi2 - lo2);

    float f[2 * NLEV];

#pragma unroll
    for (int l = 0; l < NLEV; l++) {
        float r  = c_res[l];
        float p0 = xn0 * r, p1v = xn1 * r, p2v = xn2 * r;
        float b0 = floorf(p0), b1 = floorf(p1v), b2 = floorf(p2v);
        float fr0 = p0 - b0, fr1 = p1v - b1, fr2 = p2v - b2;

        // smoothstep interpolation weights
        float w0 = fr0 * fr0 * (3.0f - 2.0f * fr0);
        float w1 = fr1 * fr1 * (3.0f - 2.0f * fr1);
        float w2 = fr2 * fr2 * (3.0f - 2.0f * fr2);
        float u0 = 1.0f - w0, u1 = 1.0f - w1, u2 = 1.0f - w2;

        unsigned c0 = (unsigned)b0, c1 = (unsigned)b1, c2 = (unsigned)b2;
        unsigned hx0 = c0,            hx1 = c0 + 1u;
        unsigned hy0 = c1 * PRIME1,   hy1 = hy0 + PRIME1;   // wraps mod 2^32
        unsigned hz0 = c2 * PRIME2,   hz1 = hz0 + PRIME2;

        const float2* tl = reinterpret_cast<const float2*>(tables) + ((size_t)l << 19);

        // issue all 8 independent gathers up front (MLP=8 to hide L2 latency)
        unsigned i000 = (hx0 ^ hy0 ^ hz0) & TMASK;
        unsigned i001 = (hx0 ^ hy0 ^ hz1) & TMASK;
        unsigned i010 = (hx0 ^ hy1 ^ hz0) & TMASK;
        unsigned i011 = (hx0 ^ hy1 ^ hz1) & TMASK;
        unsigned i100 = (hx1 ^ hy0 ^ hz0) & TMASK;
        unsigned i101 = (hx1 ^ hy0 ^ hz1) & TMASK;
        unsigned i110 = (hx1 ^ hy1 ^ hz0) & TMASK;
        unsigned i111 = (hx1 ^ hy1 ^ hz1) & TMASK;

        float2 t000 = __ldg(tl + i000);
        float2 t001 = __ldg(tl + i001);
        float2 t010 = __ldg(tl + i010);
        float2 t011 = __ldg(tl + i011);
        float2 t100 = __ldg(tl + i100);
        float2 t101 = __ldg(tl + i101);
        float2 t110 = __ldg(tl + i110);
        float2 t111 = __ldg(tl + i111);

        float w00 = u0 * u1, w01 = u0 * w1, w10 = w0 * u1, w11 = w0 * w1;
        float w000 = w00 * u2, w001 = w00 * w2;
        float w010 = w01 * u2, w011 = w01 * w2;
        float w100 = w10 * u2, w101 = w10 * w2;
        float w110 = w11 * u2, w111 = w11 * w2;

        float a0 = w000 * t000.x; float a1 = w000 * t000.y;
        a0 = fmaf(w001, t001.x, a0); a1 = fmaf(w001, t001.y, a1);
        a0 = fmaf(w010, t010.x, a0); a1 = fmaf(w010, t010.y, a1);
        a0 = fmaf(w011, t011.x, a0); a1 = fmaf(w011, t011.y, a1);
        a0 = fmaf(w100, t100.x, a0); a1 = fmaf(w100, t100.y, a1);
        a0 = fmaf(w101, t101.x, a0); a1 = fmaf(w101, t101.y, a1);
        a0 = fmaf(w110, t110.x, a0); a1 = fmaf(w110, t110.y, a1);
        a0 = fmaf(w111, t111.x, a0); a1 = fmaf(w111, t111.y, a1);

        f[2 * l]     = a0;
        f[2 * l + 1] = a1;
    }

    // 28 floats = 7 float4, row offset p*112 bytes is 16B aligned
    float4* o = reinterpret_cast<float4*>(g_feats + (size_t)p * 28);
#pragma unroll
    for (int q = 0; q < 7; q++)
        o[q] = make_float4(f[4 * q], f[4 * q + 1], f[4 * q + 2], f[4 * q + 3]);
}

// ---------------------------------------------------------------------------
// Kernel 2: MLP 36->64->64->3 (tanh) + residual + bbox rescale.
// Weights transposed into smem (row-per-output -> contiguous float4 reads).
// Fully unrolled so in[]/h1[]/h2[] stay in registers.
// ---------------------------------------------------------------------------
__global__ void __launch_bounds__(128)
mlp_kernel(const float* __restrict__ x,
           const float* __restrict__ e,
           const float* __restrict__ W1, const float* __restrict__ b1,
           const float* __restrict__ W2, const float* __restrict__ b2,
           const float* __restrict__ W3, const float* __restrict__ b3,
           const float* __restrict__ bbox,
           float* __restrict__ out,
           int n)
{
    __shared__ float sW1[W * DIN];   // [j][i], row stride 36 floats = 144B (16B-mult)
    __shared__ float sW2[W * W];     // [j][i]
    __shared__ float sW3[3 * W];     // [k][i]
    __shared__ float sb1[W], sb2[W], sb3[3];

    int tid = threadIdx.x;
    for (int t = tid; t < DIN * W; t += blockDim.x) {
        int i = t / W, j = t % W;
        sW1[j * DIN + i] = W1[t];
    }
    for (int t = tid; t < W * W; t += blockDim.x) {
        int i = t >> 6, j = t & 63;
        sW2[j * W + i] = W2[t];
    }
    for (int t = tid; t < 3 * W; t += blockDim.x) {
        int i = t / 3, j = t % 3;
        sW3[j * W + i] = W3[t];
    }
    if (tid < W) { sb1[tid] = b1[tid]; sb2[tid] = b2[tid]; }
    if (tid < 3) sb3[tid] = b3[tid];
    __syncthreads();

    int p = blockIdx.x * blockDim.x + tid;
    if (p >= n) return;

    float in[DIN];
    const float4* fp = reinterpret_cast<const float4*>(g_feats + (size_t)p * 28);
#pragma unroll
    for (int q = 0; q < 7; q++) {
        float4 v = fp[q];
        in[4 * q + 0] = v.x; in[4 * q + 1] = v.y;
        in[4 * q + 2] = v.z; in[4 * q + 3] = v.w;
    }
    const float4* ep = reinterpret_cast<const float4*>(e + (size_t)p * 8);
#pragma unroll
    for (int q = 0; q < 2; q++) {
        float4 v = ep[q];
        in[28 + 4 * q + 0] = v.x; in[28 + 4 * q + 1] = v.y;
        in[28 + 4 * q + 2] = v.z; in[28 + 4 * q + 3] = v.w;
    }

    // Layer 1: 36 -> 64, tanh
    float h1[W];
#pragma unroll
    for (int j = 0; j < W; j++) {
        float acc = sb1[j];
        const float4* wr = reinterpret_cast<const float4*>(&sW1[j * DIN]);
#pragma unroll
        for (int q = 0; q < DIN / 4; q++) {
            float4 w = wr[q];
            acc = fmaf(in[4 * q + 0], w.x, acc);
            acc = fmaf(in[4 * q + 1], w.y, acc);
            acc = fmaf(in[4 * q + 2], w.z, acc);
            acc = fmaf(in[4 * q + 3], w.w, acc);
        }
        h1[j] = tanhf(acc);
    }

    // Layer 2: 64 -> 64, tanh
    float h2[W];
#pragma unroll
    for (int j = 0; j < W; j++) {
        float acc = sb2[j];
        const float4* wr = reinterpret_cast<const float4*>(&sW2[j * W]);
#pragma unroll
        for (int q = 0; q < W / 4; q++) {
            float4 w = wr[q];
            acc = fmaf(h1[4 * q + 0], w.x, acc);
            acc = fmaf(h1[4 * q + 1], w.y, acc);
            acc = fmaf(h1[4 * q + 2], w.z, acc);
            acc = fmaf(h1[4 * q + 3], w.w, acc);
        }
        h2[j] = tanhf(acc);
    }

    // Layer 3: 64 -> 3, + residual xn, rescale to bbox
    float lo[3], hi[3];
#pragma unroll
    for (int k = 0; k < 3; k++) { lo[k] = __ldg(bbox + k); hi[k] = __ldg(bbox + 3 + k); }

    float xv[3];
#pragma unroll
    for (int k = 0; k < 3; k++) xv[k] = __ldg(x + (size_t)p * 3 + k);

#pragma unroll
    for (int k = 0; k < 3; k++) {
        float acc = sb3[k];
        const float4* wr = reinterpret_cast<const float4*>(&sW3[k * W]);
#pragma unroll
        for (int q = 0; q < W / 4; q++) {
            float4 w = wr[q];
            acc = fmaf(h2[4 * q + 0], w.x, acc);
            acc = fmaf(h2[4 * q + 1], w.y, acc);
            acc = fmaf(h2[4 * q + 2], w.z, acc);
            acc = fmaf(h2[4 * q + 3], w.w, acc);
        }
        float scale = hi[k] - lo[k];
        float xn    = (xv[k] - lo[k]) / scale;
        out[(size_t)p * 3 + k] = (acc + xn) * scale + lo[k];
    }
}

// ---------------------------------------------------------------------------
// kernel_launch: two launches, graph-capturable, allocation-free.
// Input order (metadata): x, e, tables, W1, b1, W2, b2, W3, b3, bounding_box
// ---------------------------------------------------------------------------
extern "C" void kernel_launch(void* const* d_in, const int* in_sizes, int n_in,
                              void* d_out, int out_size)
{
    const float* x      = (const float*)d_in[0];
    const float* e      = (const float*)d_in[1];
    const float* tables = (const float*)d_in[2];
    const float* W1     = (const float*)d_in[3];
    const float* b1     = (const float*)d_in[4];
    const float* W2     = (const float*)d_in[5];
    const float* b2     = (const float*)d_in[6];
    const float* W3     = (const float*)d_in[7];
    const float* b3     = (const float*)d_in[8];
    const float* bbox   = (const float*)d_in[9];

    int n = in_sizes[0] / 3;
    if (n > MAXN) n = MAXN;

    int eb = 256;
    encode_kernel<<<(n + eb - 1) / eb, eb>>>(x, tables, bbox, n);

    int mb = 128;
    mlp_kernel<<<(n + mb - 1) / mb, mb>>>(x, e, W1, b1, W2, b2, W3, b3, bbox,
                                          (float*)d_out, n);
}

// round 4
// speedup vs baseline: 1.8254x; 1.8254x over previous
#include <cuda_runtime.h>
#include <cstdint>

#define NLEV   14
#define TMASK  524287u        // (1<<19)-1
#define PRIME1 2654435761u
#define PRIME2 805459861u
#define MAXN   500000
#define DIN    36
#define W      64

// Scratch for encoded features [N, 28] (bss, not an allocation)
__device__ float g_feats[(size_t)MAXN * 28];

// floor(16 * 1.32^l), l = 0..13
__device__ __constant__ float c_res[NLEV] =
    {16.f, 21.f, 27.f, 36.f, 48.f, 64.f, 84.f, 111.f,
     147.f, 194.f, 256.f, 339.f, 447.f, 590.f};

// ---------------------------------------------------------------------------
// Packed f32x2 helpers (Blackwell FFMA2 — only reachable via PTX)
// ---------------------------------------------------------------------------
__device__ __forceinline__ unsigned long long pack2(float a, float b) {
    unsigned long long r;
    asm("mov.b64 %0, {%1, %2};" : "=l"(r) : "f"(a), "f"(b));
    return r;
}
__device__ __forceinline__ unsigned long long fma2(unsigned long long a,
                                                   unsigned long long b,
                                                   unsigned long long c) {
    unsigned long long d;
    asm("fma.rn.f32x2 %0, %1, %2, %3;" : "=l"(d) : "l"(a), "l"(b), "l"(c));
    return d;
}
__device__ __forceinline__ float2 unpack2(unsigned long long v) {
    float2 r;
    asm("mov.b64 {%0, %1}, %2;" : "=f"(r.x), "=f"(r.y) : "l"(v));
    return r;
}
__device__ __forceinline__ float tanh_hw(float x) {
    float y;
    asm("tanh.approx.f32 %0, %1;" : "=f"(y) : "f"(x));
    return y;
}

// ---------------------------------------------------------------------------
// Kernel 1: hash-grid encode (unchanged — within 12% of L2-gather floor)
// ---------------------------------------------------------------------------
__global__ void __launch_bounds__(256)
encode_kernel(const float* __restrict__ x,
              const float* __restrict__ tables,
              const float* __restrict__ bbox,
              int n)
{
    int p = blockIdx.x * blockDim.x + threadIdx.x;
    if (p >= n) return;

    float lo0 = __ldg(bbox + 0), lo1 = __ldg(bbox + 1), lo2 = __ldg(bbox + 2);
    float hi0 = __ldg(bbox + 3), hi1 = __ldg(bbox + 4), hi2 = __ldg(bbox + 5);

    float xv0 = __ldg(x + (size_t)p * 3 + 0);
    float xv1 = __ldg(x + (size_t)p * 3 + 1);
    float xv2 = __ldg(x + (size_t)p * 3 + 2);

    float xn0 = (xv0 - lo0) / (hi0 - lo0);
    float xn1 = (xv1 - lo1) / (hi1 - lo1);
    float xn2 = (xv2 - lo2) / (hi2 - lo2);

    float f[2 * NLEV];

#pragma unroll
    for (int l = 0; l < NLEV; l++) {
        float r  = c_res[l];
        float p0 = xn0 * r, p1v = xn1 * r, p2v = xn2 * r;
        float b0 = floorf(p0), b1 = floorf(p1v), b2 = floorf(p2v);
        float fr0 = p0 - b0, fr1 = p1v - b1, fr2 = p2v - b2;

        float w0 = fr0 * fr0 * (3.0f - 2.0f * fr0);
        float w1 = fr1 * fr1 * (3.0f - 2.0f * fr1);
        float w2 = fr2 * fr2 * (3.0f - 2.0f * fr2);
        float u0 = 1.0f - w0, u1 = 1.0f - w1, u2 = 1.0f - w2;

        unsigned c0 = (unsigned)b0, c1 = (unsigned)b1, c2 = (unsigned)b2;
        unsigned hx0 = c0,            hx1 = c0 + 1u;
        unsigned hy0 = c1 * PRIME1,   hy1 = hy0 + PRIME1;
        unsigned hz0 = c2 * PRIME2,   hz1 = hz0 + PRIME2;

        const float2* tl = reinterpret_cast<const float2*>(tables) + ((size_t)l << 19);

        unsigned i000 = (hx0 ^ hy0 ^ hz0) & TMASK;
        unsigned i001 = (hx0 ^ hy0 ^ hz1) & TMASK;
        unsigned i010 = (hx0 ^ hy1 ^ hz0) & TMASK;
        unsigned i011 = (hx0 ^ hy1 ^ hz1) & TMASK;
        unsigned i100 = (hx1 ^ hy0 ^ hz0) & TMASK;
        unsigned i101 = (hx1 ^ hy0 ^ hz1) & TMASK;
        unsigned i110 = (hx1 ^ hy1 ^ hz0) & TMASK;
        unsigned i111 = (hx1 ^ hy1 ^ hz1) & TMASK;

        float2 t000 = __ldg(tl + i000);
        float2 t001 = __ldg(tl + i001);
        float2 t010 = __ldg(tl + i010);
        float2 t011 = __ldg(tl + i011);
        float2 t100 = __ldg(tl + i100);
        float2 t101 = __ldg(tl + i101);
        float2 t110 = __ldg(tl + i110);
        float2 t111 = __ldg(tl + i111);

        float w00 = u0 * u1, w01 = u0 * w1, w10 = w0 * u1, w11 = w0 * w1;
        float w000 = w00 * u2, w001 = w00 * w2;
        float w010 = w01 * u2, w011 = w01 * w2;
        float w100 = w10 * u2, w101 = w10 * w2;
        float w110 = w11 * u2, w111 = w11 * w2;

        float a0 = w000 * t000.x; float a1 = w000 * t000.y;
        a0 = fmaf(w001, t001.x, a0); a1 = fmaf(w001, t001.y, a1);
        a0 = fmaf(w010, t010.x, a0); a1 = fmaf(w010, t010.y, a1);
        a0 = fmaf(w011, t011.x, a0); a1 = fmaf(w011, t011.y, a1);
        a0 = fmaf(w100, t100.x, a0); a1 = fmaf(w100, t100.y, a1);
        a0 = fmaf(w101, t101.x, a0); a1 = fmaf(w101, t101.y, a1);
        a0 = fmaf(w110, t110.x, a0); a1 = fmaf(w110, t110.y, a1);
        a0 = fmaf(w111, t111.x, a0); a1 = fmaf(w111, t111.y, a1);

        f[2 * l]     = a0;
        f[2 * l + 1] = a1;
    }

    float4* o = reinterpret_cast<float4*>(g_feats + (size_t)p * 28);
#pragma unroll
    for (int q = 0; q < 7; q++)
        o[q] = make_float4(f[4 * q], f[4 * q + 1], f[4 * q + 2], f[4 * q + 3]);
}

// ---------------------------------------------------------------------------
// Kernel 2: MLP with packed f32x2 FMAs over the output-neuron dimension.
// Weights stay in NATURAL [in][out] layout (j contiguous) so (w[j],w[j+1])
// pairs come straight out of an LDS.128. Input scalar broadcast-packed once
// per i and reused across 32 j-pairs. HW tanh.approx for activations.
// ---------------------------------------------------------------------------
__global__ void __launch_bounds__(128)
mlp_kernel(const float* __restrict__ x,
           const float* __restrict__ e,
           const float* __restrict__ W1, const float* __restrict__ b1,
           const float* __restrict__ W2, const float* __restrict__ b2,
           const float* __restrict__ W3, const float* __restrict__ b3,
           const float* __restrict__ bbox,
           float* __restrict__ out,
           int n)
{
    __shared__ __align__(16) float sW1[DIN * W];  // natural layout [i][j]
    __shared__ __align__(16) float sW2[W * W];    // natural layout [i][j]
    __shared__ __align__(16) float sW3[3 * W];    // transposed [k][i]
    __shared__ float sb1[W], sb2[W], sb3[3];

    int tid = threadIdx.x;
    for (int t = tid; t < DIN * W; t += blockDim.x) sW1[t] = W1[t];
    for (int t = tid; t < W * W;  t += blockDim.x) sW2[t] = W2[t];
    for (int t = tid; t < 3 * W;  t += blockDim.x) {
        int i = t / 3, k = t % 3;
        sW3[k * W + i] = W3[t];
    }
    if (tid < W) { sb1[tid] = b1[tid]; sb2[tid] = b2[tid]; }
    if (tid < 3) sb3[tid] = b3[tid];
    __syncthreads();

    int p = blockIdx.x * blockDim.x + tid;
    if (p >= n) return;

    // ---- load inputs (28 feats + 8 e) ----
    float in[DIN];
    const float4* fp = reinterpret_cast<const float4*>(g_feats + (size_t)p * 28);
#pragma unroll
    for (int q = 0; q < 7; q++) {
        float4 v = fp[q];
        in[4 * q + 0] = v.x; in[4 * q + 1] = v.y;
        in[4 * q + 2] = v.z; in[4 * q + 3] = v.w;
    }
    const float4* ep = reinterpret_cast<const float4*>(e + (size_t)p * 8);
#pragma unroll
    for (int q = 0; q < 2; q++) {
        float4 v = ep[q];
        in[28 + 4 * q + 0] = v.x; in[28 + 4 * q + 1] = v.y;
        in[28 + 4 * q + 2] = v.z; in[28 + 4 * q + 3] = v.w;
    }

    // ---- Layer 1: 36 -> 64 (packed pairs over j) ----
    unsigned long long acc[W / 2];
#pragma unroll
    for (int j2 = 0; j2 < W / 2; j2++)
        acc[j2] = pack2(sb1[2 * j2], sb1[2 * j2 + 1]);

#pragma unroll
    for (int i = 0; i < DIN; i++) {
        unsigned long long xi = pack2(in[i], in[i]);
        const ulonglong2* row = reinterpret_cast<const ulonglong2*>(&sW1[i * W]);
#pragma unroll
        for (int j4 = 0; j4 < W / 4; j4++) {
            ulonglong2 w = row[j4];
            acc[2 * j4 + 0] = fma2(xi, w.x, acc[2 * j4 + 0]);
            acc[2 * j4 + 1] = fma2(xi, w.y, acc[2 * j4 + 1]);
        }
    }

    float h[W];
#pragma unroll
    for (int j2 = 0; j2 < W / 2; j2++) {
        float2 v = unpack2(acc[j2]);
        h[2 * j2 + 0] = tanh_hw(v.x);
        h[2 * j2 + 1] = tanh_hw(v.y);
    }

    // ---- Layer 2: 64 -> 64 (packed pairs over j) ----
#pragma unroll
    for (int j2 = 0; j2 < W / 2; j2++)
        acc[j2] = pack2(sb2[2 * j2], sb2[2 * j2 + 1]);

#pragma unroll
    for (int i = 0; i < W; i++) {
        unsigned long long xi = pack2(h[i], h[i]);
        const ulonglong2* row = reinterpret_cast<const ulonglong2*>(&sW2[i * W]);
#pragma unroll
        for (int j4 = 0; j4 < W / 4; j4++) {
            ulonglong2 w = row[j4];
            acc[2 * j4 + 0] = fma2(xi, w.x, acc[2 * j4 + 0]);
            acc[2 * j4 + 1] = fma2(xi, w.y, acc[2 * j4 + 1]);
        }
    }

#pragma unroll
    for (int j2 = 0; j2 < W / 2; j2++) {
        float2 v = unpack2(acc[j2]);
        h[2 * j2 + 0] = tanh_hw(v.x);
        h[2 * j2 + 1] = tanh_hw(v.y);
    }

    // ---- Layer 3: 64 -> 3, + residual xn, rescale to bbox ----
    float lo[3], hi[3], xv[3];
#pragma unroll
    for (int k = 0; k < 3; k++) { lo[k] = __ldg(bbox + k); hi[k] = __ldg(bbox + 3 + k); }
#pragma unroll
    for (int k = 0; k < 3; k++) xv[k] = __ldg(x + (size_t)p * 3 + k);

#pragma unroll
    for (int k = 0; k < 3; k++) {
        float a = sb3[k];
        const float4* wr = reinterpret_cast<const float4*>(&sW3[k * W]);
#pragma unroll
        for (int q = 0; q < W / 4; q++) {
            float4 w = wr[q];
            a = fmaf(h[4 * q + 0], w.x, a);
            a = fmaf(h[4 * q + 1], w.y, a);
            a = fmaf(h[4 * q + 2], w.z, a);
            a = fmaf(h[4 * q + 3], w.w, a);
        }
        float scale = hi[k] - lo[k];
        float xn    = (xv[k] - lo[k]) / scale;
        out[(size_t)p * 3 + k] = (a + xn) * scale + lo[k];
    }
}

// ---------------------------------------------------------------------------
// kernel_launch: two launches, graph-capturable, allocation-free.
// Input order: x, e, tables, W1, b1, W2, b2, W3, b3, bounding_box
// ---------------------------------------------------------------------------
extern "C" void kernel_launch(void* const* d_in, const int* in_sizes, int n_in,
                              void* d_out, int out_size)
{
    const float* x      = (const float*)d_in[0];
    const float* e      = (const float*)d_in[1];
    const float* tables = (const float*)d_in[2];
    const float* W1     = (const float*)d_in[3];
    const float* b1     = (const float*)d_in[4];
    const float* W2     = (const float*)d_in[5];
    const float* b2     = (const float*)d_in[6];
    const float* W3     = (const float*)d_in[7];
    const float* b3     = (const float*)d_in[8];
    const float* bbox   = (const float*)d_in[9];

    int n = in_sizes[0] / 3;
    if (n > MAXN) n = MAXN;

    int eb = 256;
    encode_kernel<<<(n + eb - 1) / eb, eb>>>(x, tables, bbox, n);

    int mb = 128;
    mlp_kernel<<<(n + mb - 1) / mb, mb>>>(x, e, W1, b1, W2, b2, W3, b3, bbox,
                                          (float*)d_out, n);
}